// round 1
// baseline (speedup 1.0000x reference)
#include <cuda_runtime.h>
#include <math.h>

#define NN 4096
#define EE 1024
#define HH 16
#define VV 32
#define LL 6
#define HV 512
#define E2 2048

// ---------------- scratch (static device globals; no allocations) -------------
__device__ float g_z [NN * EE];   // residual stream
__device__ float g_q [HH * NN * VV];
__device__ float g_k [HH * NN * VV];
__device__ float g_v [HH * NN * VV];
__device__ float g_o [NN * HV];   // concat heads [N, H*V]
__device__ float g_an[NN * EE];   // post-attn layernorm
__device__ float g_h1[NN * E2];   // FF hidden
__device__ float g_u [NN * EE];   // pre-LN sum

// ------------------------------- embedding ------------------------------------
__global__ void embed_kernel(const int* __restrict__ ctx,
                             const float* __restrict__ table,
                             const float* __restrict__ pos) {
    int n = blockIdx.x;
    int t = threadIdx.x;
    int idx = ctx[n];
    const float* tr = table + (size_t)idx * EE;
    const float* pr = pos + (size_t)n * EE;
    float* zr = g_z + (size_t)n * EE;
#pragma unroll
    for (int i = 0; i < 4; i++) {
        int e = t + i * 256;
        zr[e] = tr[e] + pr[e];
    }
}

// ------------------------------- QKV projection -------------------------------
// out[h][n][v] = sum_e z[n][e] * W[l][h][e][v]   (W per blockIdx.z in {Wq,Wk,Wv})
__global__ __launch_bounds__(256) void qkv_kernel(const float* __restrict__ Wq,
                                                  const float* __restrict__ Wk,
                                                  const float* __restrict__ Wv,
                                                  int layer) {
    __shared__ float Zs[32][68];  // [kk][row]  (transposed for vector reads)
    __shared__ float Ws[32][36];  // [kk][v]
    int tid = threadIdx.x;
    int h = blockIdx.y;
    int which = blockIdx.z;
    int m0 = blockIdx.x * 64;
    const float* W = (which == 0 ? Wq : which == 1 ? Wk : Wv)
                     + ((size_t)(layer * HH + h)) * EE * VV;
    float* outp = (which == 0 ? g_q : which == 1 ? g_k : g_v)
                  + ((size_t)h * NN + m0) * VV;
    int rg = tid >> 4;          // 0..15 -> rows rg*4..rg*4+3
    int cg = tid & 15;          // 0..15 -> cols cg*2, cg*2+1
    int zr = tid >> 3;          // 0..31
    int zc = (tid & 7) * 4;
    float acc[4][2] = {};
    for (int k0 = 0; k0 < EE; k0 += 32) {
        float4 za = *(const float4*)&g_z[(size_t)(m0 + zr) * EE + k0 + zc];
        float4 zb = *(const float4*)&g_z[(size_t)(m0 + zr + 32) * EE + k0 + zc];
        float4 wv = *(const float4*)&W[(size_t)(k0 + zr) * VV + zc];
        __syncthreads();
        Zs[zc + 0][zr] = za.x; Zs[zc + 1][zr] = za.y;
        Zs[zc + 2][zr] = za.z; Zs[zc + 3][zr] = za.w;
        Zs[zc + 0][zr + 32] = zb.x; Zs[zc + 1][zr + 32] = zb.y;
        Zs[zc + 2][zr + 32] = zb.z; Zs[zc + 3][zr + 32] = zb.w;
        *(float4*)&Ws[zr][zc] = wv;
        __syncthreads();
#pragma unroll 8
        for (int kk = 0; kk < 32; kk++) {
            float4 a = *(const float4*)&Zs[kk][rg * 4];
            float2 b = *(const float2*)&Ws[kk][cg * 2];
            acc[0][0] += a.x * b.x; acc[0][1] += a.x * b.y;
            acc[1][0] += a.y * b.x; acc[1][1] += a.y * b.y;
            acc[2][0] += a.z * b.x; acc[2][1] += a.z * b.y;
            acc[3][0] += a.w * b.x; acc[3][1] += a.w * b.y;
        }
    }
#pragma unroll
    for (int i = 0; i < 4; i++)
        *(float2*)&outp[(size_t)(rg * 4 + i) * VV + cg * 2] =
            make_float2(acc[i][0], acc[i][1]);
}

// ------------------------------- flash attention ------------------------------
// Per block: one head, 64 queries. Online softmax over 64-key tiles.
__global__ __launch_bounds__(256) void attn_kernel() {
    __shared__ float Qs[32][68];     // [d][qi], pre-scaled by 1/sqrt(V)
    __shared__ float Ks[32][68];     // [d][kj]
    __shared__ float Vs[64][36];     // [kj][d]
    __shared__ float Ssh[64][68];    // S transposed: [kj][qi]; later holds P
    __shared__ float m_s[64], l_s[64], corr_s[64];
    int tid = threadIdx.x;
    int h = blockIdx.y;
    int q0 = blockIdx.x * 64;
    const float scale = 0.17677669529663687f;  // 1/sqrt(32)
    int r8 = tid >> 3;             // 0..31
    int c4 = (tid & 7) * 4;
    const float* qb = g_q + (size_t)h * NN * VV;
    const float* kb = g_k + (size_t)h * NN * VV;
    const float* vb = g_v + (size_t)h * NN * VV;
    {
        float4 qa = *(const float4*)&qb[(size_t)(q0 + r8) * VV + c4];
        float4 qc = *(const float4*)&qb[(size_t)(q0 + r8 + 32) * VV + c4];
        Qs[c4 + 0][r8] = qa.x * scale; Qs[c4 + 1][r8] = qa.y * scale;
        Qs[c4 + 2][r8] = qa.z * scale; Qs[c4 + 3][r8] = qa.w * scale;
        Qs[c4 + 0][r8 + 32] = qc.x * scale; Qs[c4 + 1][r8 + 32] = qc.y * scale;
        Qs[c4 + 2][r8 + 32] = qc.z * scale; Qs[c4 + 3][r8 + 32] = qc.w * scale;
    }
    if (tid < 64) { m_s[tid] = -INFINITY; l_s[tid] = 0.f; }
    int rg = tid >> 4;             // output rows rg*4+i
    int cg = tid & 15;             // output cols cg*2+j
    int sq = (tid >> 4) * 4;       // S-compute: qi block
    int sk = (tid & 15) * 4;       // S-compute: kj block
    int row = tid >> 2, part = tid & 3;   // softmax: 4 threads per query row
    float oacc[4][2] = {};
    __syncthreads();

    for (int kt = 0; kt < NN / 64; kt++) {
        int k0 = kt * 64;
        float4 ka = *(const float4*)&kb[(size_t)(k0 + r8) * VV + c4];
        float4 kc = *(const float4*)&kb[(size_t)(k0 + r8 + 32) * VV + c4];
        float4 va = *(const float4*)&vb[(size_t)(k0 + r8) * VV + c4];
        float4 vc = *(const float4*)&vb[(size_t)(k0 + r8 + 32) * VV + c4];
        __syncthreads();
        Ks[c4 + 0][r8] = ka.x; Ks[c4 + 1][r8] = ka.y;
        Ks[c4 + 2][r8] = ka.z; Ks[c4 + 3][r8] = ka.w;
        Ks[c4 + 0][r8 + 32] = kc.x; Ks[c4 + 1][r8 + 32] = kc.y;
        Ks[c4 + 2][r8 + 32] = kc.z; Ks[c4 + 3][r8 + 32] = kc.w;
        *(float4*)&Vs[r8][c4] = va;
        *(float4*)&Vs[r8 + 32][c4] = vc;
        __syncthreads();

        // S = Q K^T (scaled), 4x4 register tile per thread
        float s[4][4] = {};
#pragma unroll 8
        for (int d = 0; d < 32; d++) {
            float4 a = *(const float4*)&Qs[d][sq];
            float4 b = *(const float4*)&Ks[d][sk];
            s[0][0] += a.x * b.x; s[0][1] += a.x * b.y; s[0][2] += a.x * b.z; s[0][3] += a.x * b.w;
            s[1][0] += a.y * b.x; s[1][1] += a.y * b.y; s[1][2] += a.y * b.z; s[1][3] += a.y * b.w;
            s[2][0] += a.z * b.x; s[2][1] += a.z * b.y; s[2][2] += a.z * b.z; s[2][3] += a.z * b.w;
            s[3][0] += a.w * b.x; s[3][1] += a.w * b.y; s[3][2] += a.w * b.z; s[3][3] += a.w * b.w;
        }
#pragma unroll
        for (int j = 0; j < 4; j++)
            *(float4*)&Ssh[sk + j][sq] = make_float4(s[0][j], s[1][j], s[2][j], s[3][j]);
        __syncthreads();

        // online softmax per query row (4 threads/row, 16 keys each)
        float mx = -INFINITY;
#pragma unroll
        for (int t = 0; t < 16; t++) mx = fmaxf(mx, Ssh[part * 16 + t][row]);
        mx = fmaxf(mx, __shfl_xor_sync(0xffffffffu, mx, 1));
        mx = fmaxf(mx, __shfl_xor_sync(0xffffffffu, mx, 2));
        float mold = m_s[row];
        float mnew = fmaxf(mold, mx);
        float sum = 0.f;
#pragma unroll
        for (int t = 0; t < 16; t++) {
            float p = __expf(Ssh[part * 16 + t][row] - mnew);
            Ssh[part * 16 + t][row] = p;
            sum += p;
        }
        sum += __shfl_xor_sync(0xffffffffu, sum, 1);
        sum += __shfl_xor_sync(0xffffffffu, sum, 2);
        if (part == 0) {
            float cr = __expf(mold - mnew);
            corr_s[row] = cr;
            l_s[row] = l_s[row] * cr + sum;
            m_s[row] = mnew;
        }
        __syncthreads();

        // O = O*corr + P @ V
        float cr0 = corr_s[rg * 4 + 0], cr1 = corr_s[rg * 4 + 1];
        float cr2 = corr_s[rg * 4 + 2], cr3 = corr_s[rg * 4 + 3];
        oacc[0][0] *= cr0; oacc[0][1] *= cr0;
        oacc[1][0] *= cr1; oacc[1][1] *= cr1;
        oacc[2][0] *= cr2; oacc[2][1] *= cr2;
        oacc[3][0] *= cr3; oacc[3][1] *= cr3;
#pragma unroll 4
        for (int kj = 0; kj < 64; kj++) {
            float4 p = *(const float4*)&Ssh[kj][rg * 4];
            float2 vv = *(const float2*)&Vs[kj][cg * 2];
            oacc[0][0] += p.x * vv.x; oacc[0][1] += p.x * vv.y;
            oacc[1][0] += p.y * vv.x; oacc[1][1] += p.y * vv.y;
            oacc[2][0] += p.z * vv.x; oacc[2][1] += p.z * vv.y;
            oacc[3][0] += p.w * vv.x; oacc[3][1] += p.w * vv.y;
        }
    }
#pragma unroll
    for (int i = 0; i < 4; i++) {
        float inv = 1.f / l_s[rg * 4 + i];
        *(float2*)&g_o[(size_t)(q0 + rg * 4 + i) * HV + h * VV + cg * 2] =
            make_float2(oacc[i][0] * inv, oacc[i][1] * inv);
    }
}

// ------------------------------- generic GEMM ---------------------------------
// C[M,Nout] = A[M,K] @ B[K,Nout]  (+bias) (+leaky) (+res). BM=BN=64, BK=16.
template <bool LEAKY, bool HAS_BIAS, bool HAS_RES>
__device__ __forceinline__ void gemm_core(const float* __restrict__ A,
                                          const float* __restrict__ B,
                                          const float* __restrict__ bias,
                                          const float* __restrict__ res,
                                          float* __restrict__ C,
                                          int K, int Nout) {
    __shared__ float As[16][68];   // [kk][row] transposed
    __shared__ float Bs[16][68];   // [kk][col]
    int tid = threadIdx.x;
    int m0 = blockIdx.x * 64;
    int n0 = blockIdx.y * 64;
    int tr = tid >> 4, tc = tid & 15;
    int ar = tid >> 2, ac = (tid & 3) * 4;
    int br = tid >> 4, bc = (tid & 15) * 4;
    float acc[4][4] = {};
    for (int k0 = 0; k0 < K; k0 += 16) {
        float4 av = *(const float4*)&A[(size_t)(m0 + ar) * K + k0 + ac];
        float4 bv = *(const float4*)&B[(size_t)(k0 + br) * Nout + n0 + bc];
        __syncthreads();
        As[ac + 0][ar] = av.x; As[ac + 1][ar] = av.y;
        As[ac + 2][ar] = av.z; As[ac + 3][ar] = av.w;
        *(float4*)&Bs[br][bc] = bv;
        __syncthreads();
#pragma unroll
        for (int kk = 0; kk < 16; kk++) {
            float4 a = *(const float4*)&As[kk][tr * 4];
            float4 b = *(const float4*)&Bs[kk][tc * 4];
            acc[0][0] += a.x * b.x; acc[0][1] += a.x * b.y; acc[0][2] += a.x * b.z; acc[0][3] += a.x * b.w;
            acc[1][0] += a.y * b.x; acc[1][1] += a.y * b.y; acc[1][2] += a.y * b.z; acc[1][3] += a.y * b.w;
            acc[2][0] += a.z * b.x; acc[2][1] += a.z * b.y; acc[2][2] += a.z * b.z; acc[2][3] += a.z * b.w;
            acc[3][0] += a.w * b.x; acc[3][1] += a.w * b.y; acc[3][2] += a.w * b.z; acc[3][3] += a.w * b.w;
        }
    }
#pragma unroll
    for (int i = 0; i < 4; i++) {
        size_t r = (size_t)(m0 + tr * 4 + i);
        int c = n0 + tc * 4;
        float4 v = make_float4(acc[i][0], acc[i][1], acc[i][2], acc[i][3]);
        if (HAS_BIAS) {
            v.x += bias[c + 0]; v.y += bias[c + 1];
            v.z += bias[c + 2]; v.w += bias[c + 3];
        }
        if (LEAKY) {
            v.x = v.x >= 0.f ? v.x : 0.01f * v.x;
            v.y = v.y >= 0.f ? v.y : 0.01f * v.y;
            v.z = v.z >= 0.f ? v.z : 0.01f * v.z;
            v.w = v.w >= 0.f ? v.w : 0.01f * v.w;
        }
        if (HAS_RES) {
            float4 rr = *(const float4*)&res[r * Nout + c];
            v.x += rr.x; v.y += rr.y; v.z += rr.z; v.w += rr.w;
        }
        *(float4*)&C[r * Nout + c] = v;
    }
}

__global__ __launch_bounds__(256) void gemm_wo(const float* __restrict__ B) {
    gemm_core<false, false, true>(g_o, B, nullptr, g_z, g_u, HV, EE);
}
__global__ __launch_bounds__(256) void gemm_ff1(const float* __restrict__ B,
                                                const float* __restrict__ bias) {
    gemm_core<true, true, false>(g_an, B, bias, nullptr, g_h1, EE, E2);
}
__global__ __launch_bounds__(256) void gemm_ff2(const float* __restrict__ B,
                                                const float* __restrict__ bias) {
    gemm_core<false, true, true>(g_h1, B, bias, g_an, g_u, E2, EE);
}

// ------------------------------- layernorm ------------------------------------
// mean over E, unbiased std (ddof=1), NO eps.  One block (256 thr) per row.
__device__ __forceinline__ void ln_core(const float* __restrict__ in,
                                        float* __restrict__ out) {
    __shared__ float red[9];
    int r = blockIdx.x, tid = threadIdx.x;
    const float* x = in + (size_t)r * EE;
    float v[4];
#pragma unroll
    for (int i = 0; i < 4; i++) v[i] = x[tid + i * 256];
    float s = v[0] + v[1] + v[2] + v[3];
#pragma unroll
    for (int o = 16; o > 0; o >>= 1) s += __shfl_xor_sync(0xffffffffu, s, o);
    if ((tid & 31) == 0) red[tid >> 5] = s;
    __syncthreads();
    if (tid == 0) {
        float t = 0;
        for (int i = 0; i < 8; i++) t += red[i];
        red[8] = t;
    }
    __syncthreads();
    float mean = red[8] * (1.f / 1024.f);
    float d = 0;
#pragma unroll
    for (int i = 0; i < 4; i++) { float q = v[i] - mean; d += q * q; }
#pragma unroll
    for (int o = 16; o > 0; o >>= 1) d += __shfl_xor_sync(0xffffffffu, d, o);
    __syncthreads();
    if ((tid & 31) == 0) red[tid >> 5] = d;
    __syncthreads();
    if (tid == 0) {
        float t = 0;
        for (int i = 0; i < 8; i++) t += red[i];
        red[8] = t;
    }
    __syncthreads();
    float rstd = 1.f / sqrtf(red[8] * (1.f / 1023.f));
    float* o2 = out + (size_t)r * EE;
#pragma unroll
    for (int i = 0; i < 4; i++) o2[tid + i * 256] = (v[i] - mean) * rstd;
}

__global__ __launch_bounds__(256) void ln_an_kernel() { ln_core(g_u, g_an); }
__global__ __launch_bounds__(256) void ln_z_kernel() { ln_core(g_u, g_z); }
__global__ __launch_bounds__(256) void ln_out_kernel(float* out) { ln_core(g_u, out); }

// ------------------------------- driver ---------------------------------------
extern "C" void kernel_launch(void* const* d_in, const int* in_sizes, int n_in,
                              void* d_out, int out_size) {
    const int*   context = (const int*)d_in[0];
    const float* table   = (const float*)d_in[1];
    const float* pos     = (const float*)d_in[2];
    const float* Wq      = (const float*)d_in[3];
    const float* Wk      = (const float*)d_in[4];
    const float* Wv      = (const float*)d_in[5];
    const float* Wo      = (const float*)d_in[6];
    const float* W1      = (const float*)d_in[7];
    const float* b1      = (const float*)d_in[8];
    const float* W2      = (const float*)d_in[9];
    const float* b2      = (const float*)d_in[10];
    float* out = (float*)d_out;

    embed_kernel<<<NN, 256>>>(context, table, pos);
    for (int l = 0; l < LL; l++) {
        qkv_kernel<<<dim3(NN / 64, HH, 3), 256>>>(Wq, Wk, Wv, l);
        attn_kernel<<<dim3(NN / 64, HH), 256>>>();
        gemm_wo<<<dim3(NN / 64, EE / 64), 256>>>(Wo + (size_t)l * HV * EE);
        ln_an_kernel<<<NN, 256>>>();
        gemm_ff1<<<dim3(NN / 64, E2 / 64), 256>>>(W1 + (size_t)l * EE * E2,
                                                  b1 + (size_t)l * E2);
        gemm_ff2<<<dim3(NN / 64, EE / 64), 256>>>(W2 + (size_t)l * E2 * EE,
                                                  b2 + (size_t)l * EE);
        if (l == LL - 1) ln_out_kernel<<<NN, 256>>>(out);
        else             ln_z_kernel<<<NN, 256>>>();
    }
}

// round 7
// speedup vs baseline: 1.0776x; 1.0776x over previous
#include <cuda_runtime.h>
#include <math.h>

#define NN 4096
#define EE 1024
#define HH 16
#define VV 32
#define LL 6
#define HV 512
#define E2 2048

typedef unsigned long long ull;

// ---------------- scratch (static device globals; no allocations) -------------
__device__ float g_z [NN * EE];
__device__ float g_q [HH * NN * VV];
__device__ float g_k [HH * NN * VV];
__device__ float g_v [HH * NN * VV];
__device__ float g_o [NN * HV];
__device__ float g_an[NN * EE];
__device__ float g_h1[NN * E2];
__device__ float g_u [NN * EE];

// ---------------- packed f32x2 helpers -----------------------------------------
__device__ __forceinline__ ull pk2(float x, float y) {
    ull u;
    asm("mov.b64 %0, {%1, %2};" : "=l"(u) : "f"(x), "f"(y));
    return u;
}
__device__ __forceinline__ void fma2(ull& c, ull a, ull b) {
    asm("fma.rn.f32x2 %0, %1, %2, %0;" : "+l"(c) : "l"(a), "l"(b));
}
__device__ __forceinline__ ull mul2(ull a, ull b) {
    ull d;
    asm("mul.rn.f32x2 %0, %1, %2;" : "=l"(d) : "l"(a), "l"(b));
    return d;
}
__device__ __forceinline__ float2 upk(ull u) {
    float x, y;
    asm("mov.b64 {%0, %1}, %2;" : "=f"(x), "=f"(y) : "l"(u));
    return make_float2(x, y);
}

// ------------------------------- embedding ------------------------------------
__global__ void embed_kernel(const int* __restrict__ ctx,
                             const float* __restrict__ table,
                             const float* __restrict__ pos) {
    int n = blockIdx.x;
    int t = threadIdx.x;
    int idx = ctx[n];
    const float* tr = table + (size_t)idx * EE;
    const float* pr = pos + (size_t)n * EE;
    float* zr = g_z + (size_t)n * EE;
#pragma unroll
    for (int i = 0; i < 4; i++) {
        int e = t + i * 256;
        zr[e] = tr[e] + pr[e];
    }
}

// ------------------------------- f32x2 GEMM ------------------------------------
// C[4096, NOUT] = A[4096, KTOT] @ B[KTOT, NOUT] (+bias)(+leaky)(+res).
// BM=BN=128, BK=16, 256 threads, 8x8 microtile as 8 rows x 4 packed col-pairs.
template <int KTOT, int NOUT, bool HAS_BIAS, bool LEAKY, bool HAS_RES, bool QKV>
__device__ __forceinline__ void gemm_x2_core(const float* __restrict__ A,
                                             const float* __restrict__ B,
                                             const float* __restrict__ bias,
                                             const float* __restrict__ res,
                                             float* __restrict__ C) {
    __shared__ float As[16][132];   // [k][m] transposed; 132*4 B row stride (8|,16| ok)
    __shared__ float Bs[16][132];   // [k][n]

    int tid = threadIdx.x;
    int m0 = blockIdx.x * 128, n0 = blockIdx.y * 128;
    int tr = tid >> 4, tc = tid & 15;           // compute: rows tr*8+, cols tc*8+
    int rowA = tid >> 1, colA = (tid & 1) * 8;  // A load
    int rowB = tid >> 4, colB = (tid & 15) * 8; // B load

    ull acc[8][4];
#pragma unroll
    for (int i = 0; i < 8; i++)
#pragma unroll
        for (int j = 0; j < 4; j++) acc[i][j] = 0ull;

    for (int k0 = 0; k0 < KTOT; k0 += 16) {
        float4 a0g = *(const float4*)&A[(size_t)(m0 + rowA) * KTOT + k0 + colA];
        float4 a1g = *(const float4*)&A[(size_t)(m0 + rowA) * KTOT + k0 + colA + 4];
        float4 b0g, b1g;
        {
            int kk = k0 + rowB;
            if (QKV) {
                int n = n0 + colB;
                int h = n >> 5, v = n & 31;
                b0g = *(const float4*)&B[((size_t)h * EE + kk) * VV + v];
                b1g = *(const float4*)&B[((size_t)h * EE + kk) * VV + v + 4];
            } else {
                b0g = *(const float4*)&B[(size_t)kk * NOUT + n0 + colB];
                b1g = *(const float4*)&B[(size_t)kk * NOUT + n0 + colB + 4];
            }
        }
        __syncthreads();
        As[colA + 0][rowA] = a0g.x; As[colA + 1][rowA] = a0g.y;
        As[colA + 2][rowA] = a0g.z; As[colA + 3][rowA] = a0g.w;
        As[colA + 4][rowA] = a1g.x; As[colA + 5][rowA] = a1g.y;
        As[colA + 6][rowA] = a1g.z; As[colA + 7][rowA] = a1g.w;
        *(float4*)&Bs[rowB][colB] = b0g;
        *(float4*)&Bs[rowB][colB + 4] = b1g;
        __syncthreads();
#pragma unroll
        for (int kk = 0; kk < 16; kk++) {
            float4 a0 = *(const float4*)&As[kk][tr * 8];
            float4 a1 = *(const float4*)&As[kk][tr * 8 + 4];
            ull b0 = *(const ull*)&Bs[kk][tc * 8 + 0];
            ull b1 = *(const ull*)&Bs[kk][tc * 8 + 2];
            ull b2 = *(const ull*)&Bs[kk][tc * 8 + 4];
            ull b3 = *(const ull*)&Bs[kk][tc * 8 + 6];
            ull ap[8];
            ap[0] = pk2(a0.x, a0.x); ap[1] = pk2(a0.y, a0.y);
            ap[2] = pk2(a0.z, a0.z); ap[3] = pk2(a0.w, a0.w);
            ap[4] = pk2(a1.x, a1.x); ap[5] = pk2(a1.y, a1.y);
            ap[6] = pk2(a1.z, a1.z); ap[7] = pk2(a1.w, a1.w);
#pragma unroll
            for (int i = 0; i < 8; i++) {
                fma2(acc[i][0], ap[i], b0);
                fma2(acc[i][1], ap[i], b1);
                fma2(acc[i][2], ap[i], b2);
                fma2(acc[i][3], ap[i], b3);
            }
        }
    }

#pragma unroll
    for (int i = 0; i < 8; i++) {
        size_t row = (size_t)(m0 + tr * 8 + i);
        int col = n0 + tc * 8;
        float v[8];
#pragma unroll
        for (int j = 0; j < 4; j++) {
            float2 t = upk(acc[i][j]);
            v[2 * j] = t.x; v[2 * j + 1] = t.y;
        }
        if (HAS_BIAS) {
#pragma unroll
            for (int j = 0; j < 8; j++) v[j] += bias[col + j];
        }
        if (LEAKY) {
#pragma unroll
            for (int j = 0; j < 8; j++) v[j] = v[j] >= 0.f ? v[j] : 0.01f * v[j];
        }
        if (QKV) {
            int h = col >> 5, vv = col & 31;
            float* dst = C + (size_t)h * NN * VV + row * VV + vv;
            *(float4*)dst = make_float4(v[0], v[1], v[2], v[3]);
            *(float4*)(dst + 4) = make_float4(v[4], v[5], v[6], v[7]);
        } else {
            if (HAS_RES) {
                float4 r0 = *(const float4*)&res[row * NOUT + col];
                float4 r1 = *(const float4*)&res[row * NOUT + col + 4];
                v[0] += r0.x; v[1] += r0.y; v[2] += r0.z; v[3] += r0.w;
                v[4] += r1.x; v[5] += r1.y; v[6] += r1.z; v[7] += r1.w;
            }
            *(float4*)&C[row * NOUT + col] = make_float4(v[0], v[1], v[2], v[3]);
            *(float4*)&C[row * NOUT + col + 4] = make_float4(v[4], v[5], v[6], v[7]);
        }
    }
}

__global__ __launch_bounds__(256, 1) void qkv_x2(const float* __restrict__ Wq,
                                                 const float* __restrict__ Wk,
                                                 const float* __restrict__ Wv,
                                                 int layer) {
    int which = blockIdx.z;
    const float* W = (which == 0 ? Wq : which == 1 ? Wk : Wv)
                     + (size_t)layer * HH * EE * VV;
    float* outp = which == 0 ? g_q : which == 1 ? g_k : g_v;
    gemm_x2_core<EE, HV, false, false, false, true>(g_z, W, nullptr, nullptr, outp);
}
__global__ __launch_bounds__(256, 1) void wo_x2(const float* __restrict__ B) {
    gemm_x2_core<HV, EE, false, false, true, false>(g_o, B, nullptr, g_z, g_u);
}
__global__ __launch_bounds__(256, 1) void ff1_x2(const float* __restrict__ B,
                                                 const float* __restrict__ bias) {
    gemm_x2_core<EE, E2, true, true, false, false>(g_an, B, bias, nullptr, g_h1);
}
__global__ __launch_bounds__(256, 1) void ff2_x2(const float* __restrict__ B,
                                                 const float* __restrict__ bias) {
    gemm_x2_core<E2, EE, true, false, true, false>(g_h1, B, bias, g_an, g_u);
}

// ------------------------------- flash attention (f32x2) -----------------------
// Per block: one head, 64 queries. Online softmax over 64-key tiles.
__global__ __launch_bounds__(256) void attn_kernel() {
    __shared__ float Qs[32][68];
    __shared__ float Ks[32][68];
    __shared__ float Vs[64][36];
    __shared__ float Ssh[64][68];
    __shared__ float m_s[64], l_s[64], corr_s[64];
    int tid = threadIdx.x;
    int h = blockIdx.y;
    int q0 = blockIdx.x * 64;
    const float scale = 0.17677669529663687f;  // 1/sqrt(32)
    int r8 = tid >> 3;
    int c4 = (tid & 7) * 4;
    const float* qb = g_q + (size_t)h * NN * VV;
    const float* kb = g_k + (size_t)h * NN * VV;
    const float* vb = g_v + (size_t)h * NN * VV;
    {
        float4 qa = *(const float4*)&qb[(size_t)(q0 + r8) * VV + c4];
        float4 qc = *(const float4*)&qb[(size_t)(q0 + r8 + 32) * VV + c4];
        Qs[c4 + 0][r8] = qa.x * scale; Qs[c4 + 1][r8] = qa.y * scale;
        Qs[c4 + 2][r8] = qa.z * scale; Qs[c4 + 3][r8] = qa.w * scale;
        Qs[c4 + 0][r8 + 32] = qc.x * scale; Qs[c4 + 1][r8 + 32] = qc.y * scale;
        Qs[c4 + 2][r8 + 32] = qc.z * scale; Qs[c4 + 3][r8 + 32] = qc.w * scale;
    }
    if (tid < 64) { m_s[tid] = -INFINITY; l_s[tid] = 0.f; }
    int rg = tid >> 4;
    int cg = tid & 15;
    int sq = (tid >> 4) * 4;
    int sk = (tid & 15) * 4;
    int row = tid >> 2, part = tid & 3;
    ull oacc[4] = {0ull, 0ull, 0ull, 0ull};   // 4 rows x (2 packed d-cols)
    __syncthreads();

    for (int kt = 0; kt < NN / 64; kt++) {
        int k0 = kt * 64;
        float4 ka = *(const float4*)&kb[(size_t)(k0 + r8) * VV + c4];
        float4 kc = *(const float4*)&kb[(size_t)(k0 + r8 + 32) * VV + c4];
        float4 va = *(const float4*)&vb[(size_t)(k0 + r8) * VV + c4];
        float4 vc = *(const float4*)&vb[(size_t)(k0 + r8 + 32) * VV + c4];
        __syncthreads();
        Ks[c4 + 0][r8] = ka.x; Ks[c4 + 1][r8] = ka.y;
        Ks[c4 + 2][r8] = ka.z; Ks[c4 + 3][r8] = ka.w;
        Ks[c4 + 0][r8 + 32] = kc.x; Ks[c4 + 1][r8 + 32] = kc.y;
        Ks[c4 + 2][r8 + 32] = kc.z; Ks[c4 + 3][r8 + 32] = kc.w;
        *(float4*)&Vs[r8][c4] = va;
        *(float4*)&Vs[r8 + 32][c4] = vc;
        __syncthreads();

        // S = Q K^T : 4 query rows x 2 packed key-pairs per thread
        ull sp[4][2];
#pragma unroll
        for (int i = 0; i < 4; i++) { sp[i][0] = 0ull; sp[i][1] = 0ull; }
#pragma unroll 8
        for (int d = 0; d < 32; d++) {
            float4 a = *(const float4*)&Qs[d][sq];
            float4 b = *(const float4*)&Ks[d][sk];
            ull bp0 = pk2(b.x, b.y), bp1 = pk2(b.z, b.w);
            ull ap0 = pk2(a.x, a.x), ap1 = pk2(a.y, a.y);
            ull ap2 = pk2(a.z, a.z), ap3 = pk2(a.w, a.w);
            fma2(sp[0][0], ap0, bp0); fma2(sp[0][1], ap0, bp1);
            fma2(sp[1][0], ap1, bp0); fma2(sp[1][1], ap1, bp1);
            fma2(sp[2][0], ap2, bp0); fma2(sp[2][1], ap2, bp1);
            fma2(sp[3][0], ap3, bp0); fma2(sp[3][1], ap3, bp1);
        }
        float s[4][4];
#pragma unroll
        for (int i = 0; i < 4; i++) {
            float2 t0 = upk(sp[i][0]), t1 = upk(sp[i][1]);
            s[i][0] = t0.x; s[i][1] = t0.y; s[i][2] = t1.x; s[i][3] = t1.y;
        }
#pragma unroll
        for (int j = 0; j < 4; j++)
            *(float4*)&Ssh[sk + j][sq] = make_float4(s[0][j], s[1][j], s[2][j], s[3][j]);
        __syncthreads();

        // online softmax per query row
        float mx = -INFINITY;
#pragma unroll
        for (int t = 0; t < 16; t++) mx = fmaxf(mx, Ssh[part * 16 + t][row]);
        mx = fmaxf(mx, __shfl_xor_sync(0xffffffffu, mx, 1));
        mx = fmaxf(mx, __shfl_xor_sync(0xffffffffu, mx, 2));
        float mold = m_s[row];
        float mnew = fmaxf(mold, mx);
        float sum = 0.f;
#pragma unroll
        for (int t = 0; t < 16; t++) {
            float p = __expf(Ssh[part * 16 + t][row] - mnew);
            Ssh[part * 16 + t][row] = p;
            sum += p;
        }
        sum += __shfl_xor_sync(0xffffffffu, sum, 1);
        sum += __shfl_xor_sync(0xffffffffu, sum, 2);
        if (part == 0) {
            float cr = __expf(mold - mnew);
            corr_s[row] = cr;
            l_s[row] = l_s[row] * cr + sum;
            m_s[row] = mnew;
        }
        __syncthreads();

        // O = O*corr + P @ V   (rows rg*4+i, packed col pair cg*2..cg*2+1)
        oacc[0] = mul2(oacc[0], pk2(corr_s[rg * 4 + 0], corr_s[rg * 4 + 0]));
        oacc[1] = mul2(oacc[1], pk2(corr_s[rg * 4 + 1], corr_s[rg * 4 + 1]));
        oacc[2] = mul2(oacc[2], pk2(corr_s[rg * 4 + 2], corr_s[rg * 4 + 2]));
        oacc[3] = mul2(oacc[3], pk2(corr_s[rg * 4 + 3], corr_s[rg * 4 + 3]));
#pragma unroll 8
        for (int kj = 0; kj < 64; kj++) {
            float4 p = *(const float4*)&Ssh[kj][rg * 4];
            ull vvp = *(const ull*)&Vs[kj][cg * 2];
            fma2(oacc[0], pk2(p.x, p.x), vvp);
            fma2(oacc[1], pk2(p.y, p.y), vvp);
            fma2(oacc[2], pk2(p.z, p.z), vvp);
            fma2(oacc[3], pk2(p.w, p.w), vvp);
        }
    }
#pragma unroll
    for (int i = 0; i < 4; i++) {
        float inv = 1.f / l_s[rg * 4 + i];
        float2 t = upk(oacc[i]);
        *(float2*)&g_o[(size_t)(q0 + rg * 4 + i) * HV + h * VV + cg * 2] =
            make_float2(t.x * inv, t.y * inv);
    }
}

// ------------------------------- layernorm ------------------------------------
__device__ __forceinline__ void ln_core(const float* __restrict__ in,
                                        float* __restrict__ out) {
    __shared__ float red[9];
    int r = blockIdx.x, tid = threadIdx.x;
    const float* x = in + (size_t)r * EE;
    float v[4];
#pragma unroll
    for (int i = 0; i < 4; i++) v[i] = x[tid + i * 256];
    float s = v[0] + v[1] + v[2] + v[3];
#pragma unroll
    for (int o = 16; o > 0; o >>= 1) s += __shfl_xor_sync(0xffffffffu, s, o);
    if ((tid & 31) == 0) red[tid >> 5] = s;
    __syncthreads();
    if (tid == 0) {
        float tt = 0;
        for (int i = 0; i < 8; i++) tt += red[i];
        red[8] = tt;
    }
    __syncthreads();
    float mean = red[8] * (1.f / 1024.f);
    float d = 0;
#pragma unroll
    for (int i = 0; i < 4; i++) { float q = v[i] - mean; d += q * q; }
#pragma unroll
    for (int o = 16; o > 0; o >>= 1) d += __shfl_xor_sync(0xffffffffu, d, o);
    __syncthreads();
    if ((tid & 31) == 0) red[tid >> 5] = d;
    __syncthreads();
    if (tid == 0) {
        float tt = 0;
        for (int i = 0; i < 8; i++) tt += red[i];
        red[8] = tt;
    }
    __syncthreads();
    float rstd = 1.f / sqrtf(red[8] * (1.f / 1023.f));
    float* o2 = out + (size_t)r * EE;
#pragma unroll
    for (int i = 0; i < 4; i++) o2[tid + i * 256] = (v[i] - mean) * rstd;
}

__global__ __launch_bounds__(256) void ln_an_kernel() { ln_core(g_u, g_an); }
__global__ __launch_bounds__(256) void ln_z_kernel() { ln_core(g_u, g_z); }
__global__ __launch_bounds__(256) void ln_out_kernel(float* out) { ln_core(g_u, out); }

// ------------------------------- driver ---------------------------------------
extern "C" void kernel_launch(void* const* d_in, const int* in_sizes, int n_in,
                              void* d_out, int out_size) {
    const int*   context = (const int*)d_in[0];
    const float* table   = (const float*)d_in[1];
    const float* pos     = (const float*)d_in[2];
    const float* Wq      = (const float*)d_in[3];
    const float* Wk      = (const float*)d_in[4];
    const float* Wv      = (const float*)d_in[5];
    const float* Wo      = (const float*)d_in[6];
    const float* W1      = (const float*)d_in[7];
    const float* b1      = (const float*)d_in[8];
    const float* W2      = (const float*)d_in[9];
    const float* b2      = (const float*)d_in[10];
    float* out = (float*)d_out;

    embed_kernel<<<NN, 256>>>(context, table, pos);
    for (int l = 0; l < LL; l++) {
        qkv_x2<<<dim3(NN / 128, HV / 128, 3), 256>>>(Wq, Wk, Wv, l);
        attn_kernel<<<dim3(NN / 64, HH), 256>>>();
        wo_x2<<<dim3(NN / 128, EE / 128), 256>>>(Wo + (size_t)l * HV * EE);
        ln_an_kernel<<<NN, 256>>>();
        ff1_x2<<<dim3(NN / 128, E2 / 128), 256>>>(W1 + (size_t)l * EE * E2,
                                                  b1 + (size_t)l * E2);
        ff2_x2<<<dim3(NN / 128, EE / 128), 256>>>(W2 + (size_t)l * E2 * EE,
                                                  b2 + (size_t)l * EE);
        if (l == LL - 1) ln_out_kernel<<<NN, 256>>>(out);
        else             ln_z_kernel<<<NN, 256>>>();
    }
}

// round 9
// speedup vs baseline: 1.1598x; 1.0763x over previous
#include <cuda_runtime.h>
#include <math.h>

#define NN 4096
#define EE 1024
#define HH 16
#define VV 32
#define LL 6
#define HV 512
#define E2 2048

typedef unsigned long long ull;

// ---------------- scratch (static device globals; no allocations) -------------
__device__ float g_z [NN * EE];
__device__ float g_q [HH * NN * VV];
__device__ float g_k [HH * NN * VV];
__device__ float g_v [HH * NN * VV];
__device__ float g_o [NN * HV];
__device__ float g_an[NN * EE];
__device__ float g_h1[NN * E2];
__device__ float g_u [NN * EE];

// ---------------- packed f32x2 helpers -----------------------------------------
__device__ __forceinline__ ull pk2(float x, float y) {
    ull u;
    asm("mov.b64 %0, {%1, %2};" : "=l"(u) : "f"(x), "f"(y));
    return u;
}
__device__ __forceinline__ void fma2(ull& c, ull a, ull b) {
    asm("fma.rn.f32x2 %0, %1, %2, %0;" : "+l"(c) : "l"(a), "l"(b));
}
__device__ __forceinline__ ull mul2(ull a, ull b) {
    ull d;
    asm("mul.rn.f32x2 %0, %1, %2;" : "=l"(d) : "l"(a), "l"(b));
    return d;
}
__device__ __forceinline__ float2 upk(ull u) {
    float x, y;
    asm("mov.b64 {%0, %1}, %2;" : "=f"(x), "=f"(y) : "l"(u));
    return make_float2(x, y);
}

// ------------------------------- embedding ------------------------------------
__global__ void embed_kernel(const int* __restrict__ ctx,
                             const float* __restrict__ table,
                             const float* __restrict__ pos) {
    int n = blockIdx.x;
    int t = threadIdx.x;
    int idx = ctx[n];
    const float* tr = table + (size_t)idx * EE;
    const float* pr = pos + (size_t)n * EE;
    float* zr = g_z + (size_t)n * EE;
#pragma unroll
    for (int i = 0; i < 4; i++) {
        int e = t + i * 256;
        zr[e] = tr[e] + pr[e];
    }
}

// ------------------------------- f32x2 GEMM ------------------------------------
// C[4096, NOUT] = A[4096, KTOT] @ B[KTOT, NOUT] (+bias)(+leaky)(+res).
// BM=BN=128, BK=16, 256 threads, 8x8 microtile as 8 rows x 4 packed col-pairs.
template <int KTOT, int NOUT, bool HAS_BIAS, bool LEAKY, bool HAS_RES, bool QKV>
__device__ __forceinline__ void gemm_x2_core(const float* __restrict__ A,
                                             const float* __restrict__ B,
                                             const float* __restrict__ bias,
                                             const float* __restrict__ res,
                                             float* __restrict__ C) {
    __shared__ float As[16][132];   // [k][m] transposed
    __shared__ float Bs[16][132];   // [k][n]

    int tid = threadIdx.x;
    int m0 = blockIdx.x * 128, n0 = blockIdx.y * 128;
    int tr = tid >> 4, tc = tid & 15;
    int rowA = tid >> 1, colA = (tid & 1) * 8;
    int rowB = tid >> 4, colB = (tid & 15) * 8;

    ull acc[8][4];
#pragma unroll
    for (int i = 0; i < 8; i++)
#pragma unroll
        for (int j = 0; j < 4; j++) acc[i][j] = 0ull;

    for (int k0 = 0; k0 < KTOT; k0 += 16) {
        float4 a0g = *(const float4*)&A[(size_t)(m0 + rowA) * KTOT + k0 + colA];
        float4 a1g = *(const float4*)&A[(size_t)(m0 + rowA) * KTOT + k0 + colA + 4];
        float4 b0g, b1g;
        {
            int kk = k0 + rowB;
            if (QKV) {
                int n = n0 + colB;
                int h = n >> 5, v = n & 31;
                b0g = *(const float4*)&B[((size_t)h * EE + kk) * VV + v];
                b1g = *(const float4*)&B[((size_t)h * EE + kk) * VV + v + 4];
            } else {
                b0g = *(const float4*)&B[(size_t)kk * NOUT + n0 + colB];
                b1g = *(const float4*)&B[(size_t)kk * NOUT + n0 + colB + 4];
            }
        }
        __syncthreads();
        As[colA + 0][rowA] = a0g.x; As[colA + 1][rowA] = a0g.y;
        As[colA + 2][rowA] = a0g.z; As[colA + 3][rowA] = a0g.w;
        As[colA + 4][rowA] = a1g.x; As[colA + 5][rowA] = a1g.y;
        As[colA + 6][rowA] = a1g.z; As[colA + 7][rowA] = a1g.w;
        *(float4*)&Bs[rowB][colB] = b0g;
        *(float4*)&Bs[rowB][colB + 4] = b1g;
        __syncthreads();
#pragma unroll
        for (int kk = 0; kk < 16; kk++) {
            float4 a0 = *(const float4*)&As[kk][tr * 8];
            float4 a1 = *(const float4*)&As[kk][tr * 8 + 4];
            ull b0 = *(const ull*)&Bs[kk][tc * 8 + 0];
            ull b1 = *(const ull*)&Bs[kk][tc * 8 + 2];
            ull b2 = *(const ull*)&Bs[kk][tc * 8 + 4];
            ull b3 = *(const ull*)&Bs[kk][tc * 8 + 6];
            ull ap[8];
            ap[0] = pk2(a0.x, a0.x); ap[1] = pk2(a0.y, a0.y);
            ap[2] = pk2(a0.z, a0.z); ap[3] = pk2(a0.w, a0.w);
            ap[4] = pk2(a1.x, a1.x); ap[5] = pk2(a1.y, a1.y);
            ap[6] = pk2(a1.z, a1.z); ap[7] = pk2(a1.w, a1.w);
#pragma unroll
            for (int i = 0; i < 8; i++) {
                fma2(acc[i][0], ap[i], b0);
                fma2(acc[i][1], ap[i], b1);
                fma2(acc[i][2], ap[i], b2);
                fma2(acc[i][3], ap[i], b3);
            }
        }
    }

#pragma unroll
    for (int i = 0; i < 8; i++) {
        size_t row = (size_t)(m0 + tr * 8 + i);
        int col = n0 + tc * 8;
        float v[8];
#pragma unroll
        for (int j = 0; j < 4; j++) {
            float2 t = upk(acc[i][j]);
            v[2 * j] = t.x; v[2 * j + 1] = t.y;
        }
        if (HAS_BIAS) {
#pragma unroll
            for (int j = 0; j < 8; j++) v[j] += bias[col + j];
        }
        if (LEAKY) {
#pragma unroll
            for (int j = 0; j < 8; j++) v[j] = v[j] >= 0.f ? v[j] : 0.01f * v[j];
        }
        if (QKV) {
            int h = col >> 5, vv = col & 31;
            float* dst = C + (size_t)h * NN * VV + row * VV + vv;
            *(float4*)dst = make_float4(v[0], v[1], v[2], v[3]);
            *(float4*)(dst + 4) = make_float4(v[4], v[5], v[6], v[7]);
        } else {
            if (HAS_RES) {
                float4 r0 = *(const float4*)&res[row * NOUT + col];
                float4 r1 = *(const float4*)&res[row * NOUT + col + 4];
                v[0] += r0.x; v[1] += r0.y; v[2] += r0.z; v[3] += r0.w;
                v[4] += r1.x; v[5] += r1.y; v[6] += r1.z; v[7] += r1.w;
            }
            *(float4*)&C[row * NOUT + col] = make_float4(v[0], v[1], v[2], v[3]);
            *(float4*)&C[row * NOUT + col + 4] = make_float4(v[4], v[5], v[6], v[7]);
        }
    }
}

__global__ __launch_bounds__(256, 1) void qkv_x2(const float* __restrict__ Wq,
                                                 const float* __restrict__ Wk,
                                                 const float* __restrict__ Wv,
                                                 int layer) {
    int which = blockIdx.z;
    const float* W = (which == 0 ? Wq : which == 1 ? Wk : Wv)
                     + (size_t)layer * HH * EE * VV;
    float* outp = which == 0 ? g_q : which == 1 ? g_k : g_v;
    gemm_x2_core<EE, HV, false, false, false, true>(g_z, W, nullptr, nullptr, outp);
}
__global__ __launch_bounds__(256, 1) void wo_x2(const float* __restrict__ B) {
    gemm_x2_core<HV, EE, false, false, true, false>(g_o, B, nullptr, g_z, g_u);
}
__global__ __launch_bounds__(256, 1) void ff1_x2(const float* __restrict__ B,
                                                 const float* __restrict__ bias) {
    gemm_x2_core<EE, E2, true, true, false, false>(g_an, B, bias, nullptr, g_h1);
}
__global__ __launch_bounds__(256, 1) void ff2_x2(const float* __restrict__ B,
                                                 const float* __restrict__ bias) {
    gemm_x2_core<E2, EE, true, false, true, false>(g_h1, B, bias, g_an, g_u);
}

// ------------------------------- flash attention -------------------------------
// Per block: one head, 64 queries, 64-key tiles. Softmax fully in registers:
// thread (tr=tid>>4, tc=tid&15) owns S tile rows tr*4..+3, keys tc*4..+3;
// the 16 lanes of a half-warp cover all 64 keys of 4 shared q-rows, so
// row max/sum reduce via shfl_xor(1,2,4,8) without touching smem. Running
// m/l live per-thread (replicated across the half-warp). Only P crosses smem.
__global__ __launch_bounds__(256) void attn_kernel() {
    __shared__ float Qs[32][68];     // [d][q], pre-scaled
    __shared__ float Ks[32][68];     // [d][key]
    __shared__ float Vs[64][36];     // [key][d]
    __shared__ float Psh[64][68];    // P transposed: [key][q]
    int tid = threadIdx.x;
    int h = blockIdx.y;
    int q0 = blockIdx.x * 64;
    const float scale = 0.17677669529663687f;  // 1/sqrt(32)
    int r8 = tid >> 3;
    int c4 = (tid & 7) * 4;
    const float* qb = g_q + (size_t)h * NN * VV;
    const float* kb = g_k + (size_t)h * NN * VV;
    const float* vb = g_v + (size_t)h * NN * VV;
    {
        float4 qa = *(const float4*)&qb[(size_t)(q0 + r8) * VV + c4];
        float4 qc = *(const float4*)&qb[(size_t)(q0 + r8 + 32) * VV + c4];
        Qs[c4 + 0][r8] = qa.x * scale; Qs[c4 + 1][r8] = qa.y * scale;
        Qs[c4 + 2][r8] = qa.z * scale; Qs[c4 + 3][r8] = qa.w * scale;
        Qs[c4 + 0][r8 + 32] = qc.x * scale; Qs[c4 + 1][r8 + 32] = qc.y * scale;
        Qs[c4 + 2][r8 + 32] = qc.z * scale; Qs[c4 + 3][r8 + 32] = qc.w * scale;
    }
    int tr = tid >> 4;             // q rows tr*4+i (S, PV, output)
    int tc = tid & 15;             // keys tc*4+j (S); d cols tc*2 (PV, output)
    int sq = tr * 4, sk = tc * 4;
    float m[4], l[4];
#pragma unroll
    for (int i = 0; i < 4; i++) { m[i] = -INFINITY; l[i] = 0.f; }
    ull oacc[4] = {0ull, 0ull, 0ull, 0ull};
    __syncthreads();

    for (int kt = 0; kt < NN / 64; kt++) {
        int k0 = kt * 64;
        float4 ka = *(const float4*)&kb[(size_t)(k0 + r8) * VV + c4];
        float4 kc = *(const float4*)&kb[(size_t)(k0 + r8 + 32) * VV + c4];
        float4 va = *(const float4*)&vb[(size_t)(k0 + r8) * VV + c4];
        float4 vc = *(const float4*)&vb[(size_t)(k0 + r8 + 32) * VV + c4];
        __syncthreads();   // prior PV done with Vs/Psh
        Ks[c4 + 0][r8] = ka.x; Ks[c4 + 1][r8] = ka.y;
        Ks[c4 + 2][r8] = ka.z; Ks[c4 + 3][r8] = ka.w;
        Ks[c4 + 0][r8 + 32] = kc.x; Ks[c4 + 1][r8 + 32] = kc.y;
        Ks[c4 + 2][r8 + 32] = kc.z; Ks[c4 + 3][r8 + 32] = kc.w;
        *(float4*)&Vs[r8][c4] = va;
        *(float4*)&Vs[r8 + 32][c4] = vc;
        __syncthreads();

        // S = Q K^T : 4 query rows x 2 packed key-pairs (f32x2)
        ull sp[4][2];
#pragma unroll
        for (int i = 0; i < 4; i++) { sp[i][0] = 0ull; sp[i][1] = 0ull; }
#pragma unroll 8
        for (int d = 0; d < 32; d++) {
            float4 a = *(const float4*)&Qs[d][sq];
            float4 b = *(const float4*)&Ks[d][sk];
            ull bp0 = pk2(b.x, b.y), bp1 = pk2(b.z, b.w);
            ull ap0 = pk2(a.x, a.x), ap1 = pk2(a.y, a.y);
            ull ap2 = pk2(a.z, a.z), ap3 = pk2(a.w, a.w);
            fma2(sp[0][0], ap0, bp0); fma2(sp[0][1], ap0, bp1);
            fma2(sp[1][0], ap1, bp0); fma2(sp[1][1], ap1, bp1);
            fma2(sp[2][0], ap2, bp0); fma2(sp[2][1], ap2, bp1);
            fma2(sp[3][0], ap3, bp0); fma2(sp[3][1], ap3, bp1);
        }
        float s[4][4];
#pragma unroll
        for (int i = 0; i < 4; i++) {
            float2 t0 = upk(sp[i][0]), t1 = upk(sp[i][1]);
            s[i][0] = t0.x; s[i][1] = t0.y; s[i][2] = t1.x; s[i][3] = t1.y;
        }

        // in-register online softmax (per q-row, reduce over 16 lanes = 64 keys)
        float corr[4];
#pragma unroll
        for (int i = 0; i < 4; i++) {
            float mx = fmaxf(fmaxf(s[i][0], s[i][1]), fmaxf(s[i][2], s[i][3]));
            mx = fmaxf(mx, __shfl_xor_sync(0xffffffffu, mx, 1));
            mx = fmaxf(mx, __shfl_xor_sync(0xffffffffu, mx, 2));
            mx = fmaxf(mx, __shfl_xor_sync(0xffffffffu, mx, 4));
            mx = fmaxf(mx, __shfl_xor_sync(0xffffffffu, mx, 8));
            float mnew = fmaxf(m[i], mx);
            float p0 = __expf(s[i][0] - mnew);
            float p1 = __expf(s[i][1] - mnew);
            float p2 = __expf(s[i][2] - mnew);
            float p3 = __expf(s[i][3] - mnew);
            s[i][0] = p0; s[i][1] = p1; s[i][2] = p2; s[i][3] = p3;
            float sum = (p0 + p1) + (p2 + p3);
            sum += __shfl_xor_sync(0xffffffffu, sum, 1);
            sum += __shfl_xor_sync(0xffffffffu, sum, 2);
            sum += __shfl_xor_sync(0xffffffffu, sum, 4);
            sum += __shfl_xor_sync(0xffffffffu, sum, 8);
            float cr = __expf(m[i] - mnew);
            corr[i] = cr;
            l[i] = l[i] * cr + sum;
            m[i] = mnew;
        }
        oacc[0] = mul2(oacc[0], pk2(corr[0], corr[0]));
        oacc[1] = mul2(oacc[1], pk2(corr[1], corr[1]));
        oacc[2] = mul2(oacc[2], pk2(corr[2], corr[2]));
        oacc[3] = mul2(oacc[3], pk2(corr[3], corr[3]));

        // exchange P through smem (transposed for PV)
#pragma unroll
        for (int j = 0; j < 4; j++)
            *(float4*)&Psh[sk + j][sq] = make_float4(s[0][j], s[1][j], s[2][j], s[3][j]);
        __syncthreads();

        // O += P @ V   (rows tr*4+i, packed d pair tc*2)
#pragma unroll 8
        for (int kj = 0; kj < 64; kj++) {
            float4 p = *(const float4*)&Psh[kj][sq];
            ull vvp = *(const ull*)&Vs[kj][tc * 2];
            fma2(oacc[0], pk2(p.x, p.x), vvp);
            fma2(oacc[1], pk2(p.y, p.y), vvp);
            fma2(oacc[2], pk2(p.z, p.z), vvp);
            fma2(oacc[3], pk2(p.w, p.w), vvp);
        }
    }
#pragma unroll
    for (int i = 0; i < 4; i++) {
        float inv = 1.f / l[i];
        float2 t = upk(oacc[i]);
        *(float2*)&g_o[(size_t)(q0 + tr * 4 + i) * HV + h * VV + tc * 2] =
            make_float2(t.x * inv, t.y * inv);
    }
}

// ------------------------------- layernorm ------------------------------------
__device__ __forceinline__ void ln_core(const float* __restrict__ in,
                                        float* __restrict__ out) {
    __shared__ float red[9];
    int r = blockIdx.x, tid = threadIdx.x;
    const float* x = in + (size_t)r * EE;
    float v[4];
#pragma unroll
    for (int i = 0; i < 4; i++) v[i] = x[tid + i * 256];
    float s = v[0] + v[1] + v[2] + v[3];
#pragma unroll
    for (int o = 16; o > 0; o >>= 1) s += __shfl_xor_sync(0xffffffffu, s, o);
    if ((tid & 31) == 0) red[tid >> 5] = s;
    __syncthreads();
    if (tid == 0) {
        float tt = 0;
        for (int i = 0; i < 8; i++) tt += red[i];
        red[8] = tt;
    }
    __syncthreads();
    float mean = red[8] * (1.f / 1024.f);
    float d = 0;
#pragma unroll
    for (int i = 0; i < 4; i++) { float q = v[i] - mean; d += q * q; }
#pragma unroll
    for (int o = 16; o > 0; o >>= 1) d += __shfl_xor_sync(0xffffffffu, d, o);
    __syncthreads();
    if ((tid & 31) == 0) red[tid >> 5] = d;
    __syncthreads();
    if (tid == 0) {
        float tt = 0;
        for (int i = 0; i < 8; i++) tt += red[i];
        red[8] = tt;
    }
    __syncthreads();
    float rstd = 1.f / sqrtf(red[8] * (1.f / 1023.f));
    float* o2 = out + (size_t)r * EE;
#pragma unroll
    for (int i = 0; i < 4; i++) o2[tid + i * 256] = (v[i] - mean) * rstd;
}

__global__ __launch_bounds__(256) void ln_an_kernel() { ln_core(g_u, g_an); }
__global__ __launch_bounds__(256) void ln_z_kernel() { ln_core(g_u, g_z); }
__global__ __launch_bounds__(256) void ln_out_kernel(float* out) { ln_core(g_u, out); }

// ------------------------------- driver ---------------------------------------
extern "C" void kernel_launch(void* const* d_in, const int* in_sizes, int n_in,
                              void* d_out, int out_size) {
    const int*   context = (const int*)d_in[0];
    const float* table   = (const float*)d_in[1];
    const float* pos     = (const float*)d_in[2];
    const float* Wq      = (const float*)d_in[3];
    const float* Wk      = (const float*)d_in[4];
    const float* Wv      = (const float*)d_in[5];
    const float* Wo      = (const float*)d_in[6];
    const float* W1      = (const float*)d_in[7];
    const float* b1      = (const float*)d_in[8];
    const float* W2      = (const float*)d_in[9];
    const float* b2      = (const float*)d_in[10];
    float* out = (float*)d_out;

    embed_kernel<<<NN, 256>>>(context, table, pos);
    for (int l = 0; l < LL; l++) {
        qkv_x2<<<dim3(NN / 128, HV / 128, 3), 256>>>(Wq, Wk, Wv, l);
        attn_kernel<<<dim3(NN / 64, HH), 256>>>();
        wo_x2<<<dim3(NN / 128, EE / 128), 256>>>(Wo + (size_t)l * HV * EE);
        ln_an_kernel<<<NN, 256>>>();
        ff1_x2<<<dim3(NN / 128, E2 / 128), 256>>>(W1 + (size_t)l * EE * E2,
                                                  b1 + (size_t)l * E2);
        ff2_x2<<<dim3(NN / 128, EE / 128), 256>>>(W2 + (size_t)l * E2 * EE,
                                                  b2 + (size_t)l * EE);
        if (l == LL - 1) ln_out_kernel<<<NN, 256>>>(out);
        else             ln_z_kernel<<<NN, 256>>>();
    }
}

// round 10
// speedup vs baseline: 1.1610x; 1.0010x over previous
#include <cuda_runtime.h>
#include <math.h>

#define NN 4096
#define EE 1024
#define HH 16
#define VV 32
#define LL 6
#define HV 512
#define E2 2048

typedef unsigned long long ull;

// ---------------- scratch (static device globals; no allocations) -------------
__device__ float g_z [NN * EE];
__device__ float g_q [HH * NN * VV];
__device__ float g_k [HH * NN * VV];
__device__ float g_v [HH * NN * VV];
__device__ float g_o [NN * HV];
__device__ float g_an[NN * EE];
__device__ float g_h1[NN * E2];
__device__ float g_u [NN * EE];

// ---------------- packed f32x2 helpers -----------------------------------------
__device__ __forceinline__ ull pk2(float x, float y) {
    ull u;
    asm("mov.b64 %0, {%1, %2};" : "=l"(u) : "f"(x), "f"(y));
    return u;
}
__device__ __forceinline__ void fma2(ull& c, ull a, ull b) {
    asm("fma.rn.f32x2 %0, %1, %2, %0;" : "+l"(c) : "l"(a), "l"(b));
}
__device__ __forceinline__ ull mul2(ull a, ull b) {
    ull d;
    asm("mul.rn.f32x2 %0, %1, %2;" : "=l"(d) : "l"(a), "l"(b));
    return d;
}
__device__ __forceinline__ float2 upk(ull u) {
    float x, y;
    asm("mov.b64 {%0, %1}, %2;" : "=f"(x), "=f"(y) : "l"(u));
    return make_float2(x, y);
}

// ------------------------------- embedding ------------------------------------
__global__ void embed_kernel(const int* __restrict__ ctx,
                             const float* __restrict__ table,
                             const float* __restrict__ pos) {
    int n = blockIdx.x;
    int t = threadIdx.x;
    int idx = ctx[n];
    const float4* tr = (const float4*)(table + (size_t)idx * EE);
    const float4* pr = (const float4*)(pos + (size_t)n * EE);
    float4* zr = (float4*)(g_z + (size_t)n * EE);
    float4 a = tr[t], b = pr[t];
    zr[t] = make_float4(a.x + b.x, a.y + b.y, a.z + b.z, a.w + b.w);
}

// ------------------------------- f32x2 GEMM ------------------------------------
// C[4096, NOUT] = A[4096, KTOT] @ B[KTOT, NOUT] (+bias)(+leaky)(+res).
// BM=BN=128, BK=16, 256 threads, 8x8 microtile as 8 rows x 4 packed col-pairs.
template <int KTOT, int NOUT, bool HAS_BIAS, bool LEAKY, bool HAS_RES, bool QKV>
__device__ __forceinline__ void gemm_x2_core(const float* __restrict__ A,
                                             const float* __restrict__ B,
                                             const float* __restrict__ bias,
                                             const float* __restrict__ res,
                                             float* __restrict__ C) {
    __shared__ float As[16][132];   // [k][m] transposed
    __shared__ float Bs[16][132];   // [k][n]

    int tid = threadIdx.x;
    int m0 = blockIdx.x * 128, n0 = blockIdx.y * 128;
    int tr = tid >> 4, tc = tid & 15;
    int rowA = tid >> 1, colA = (tid & 1) * 8;
    int rowB = tid >> 4, colB = (tid & 15) * 8;

    ull acc[8][4];
#pragma unroll
    for (int i = 0; i < 8; i++)
#pragma unroll
        for (int j = 0; j < 4; j++) acc[i][j] = 0ull;

    for (int k0 = 0; k0 < KTOT; k0 += 16) {
        float4 a0g = *(const float4*)&A[(size_t)(m0 + rowA) * KTOT + k0 + colA];
        float4 a1g = *(const float4*)&A[(size_t)(m0 + rowA) * KTOT + k0 + colA + 4];
        float4 b0g, b1g;
        {
            int kk = k0 + rowB;
            if (QKV) {
                int n = n0 + colB;
                int h = n >> 5, v = n & 31;
                b0g = *(const float4*)&B[((size_t)h * EE + kk) * VV + v];
                b1g = *(const float4*)&B[((size_t)h * EE + kk) * VV + v + 4];
            } else {
                b0g = *(const float4*)&B[(size_t)kk * NOUT + n0 + colB];
                b1g = *(const float4*)&B[(size_t)kk * NOUT + n0 + colB + 4];
            }
        }
        __syncthreads();
        As[colA + 0][rowA] = a0g.x; As[colA + 1][rowA] = a0g.y;
        As[colA + 2][rowA] = a0g.z; As[colA + 3][rowA] = a0g.w;
        As[colA + 4][rowA] = a1g.x; As[colA + 5][rowA] = a1g.y;
        As[colA + 6][rowA] = a1g.z; As[colA + 7][rowA] = a1g.w;
        *(float4*)&Bs[rowB][colB] = b0g;
        *(float4*)&Bs[rowB][colB + 4] = b1g;
        __syncthreads();
#pragma unroll
        for (int kk = 0; kk < 16; kk++) {
            float4 a0 = *(const float4*)&As[kk][tr * 8];
            float4 a1 = *(const float4*)&As[kk][tr * 8 + 4];
            ull b0 = *(const ull*)&Bs[kk][tc * 8 + 0];
            ull b1 = *(const ull*)&Bs[kk][tc * 8 + 2];
            ull b2 = *(const ull*)&Bs[kk][tc * 8 + 4];
            ull b3 = *(const ull*)&Bs[kk][tc * 8 + 6];
            ull ap[8];
            ap[0] = pk2(a0.x, a0.x); ap[1] = pk2(a0.y, a0.y);
            ap[2] = pk2(a0.z, a0.z); ap[3] = pk2(a0.w, a0.w);
            ap[4] = pk2(a1.x, a1.x); ap[5] = pk2(a1.y, a1.y);
            ap[6] = pk2(a1.z, a1.z); ap[7] = pk2(a1.w, a1.w);
#pragma unroll
            for (int i = 0; i < 8; i++) {
                fma2(acc[i][0], ap[i], b0);
                fma2(acc[i][1], ap[i], b1);
                fma2(acc[i][2], ap[i], b2);
                fma2(acc[i][3], ap[i], b3);
            }
        }
    }

#pragma unroll
    for (int i = 0; i < 8; i++) {
        size_t row = (size_t)(m0 + tr * 8 + i);
        int col = n0 + tc * 8;
        float v[8];
#pragma unroll
        for (int j = 0; j < 4; j++) {
            float2 t = upk(acc[i][j]);
            v[2 * j] = t.x; v[2 * j + 1] = t.y;
        }
        if (HAS_BIAS) {
#pragma unroll
            for (int j = 0; j < 8; j++) v[j] += bias[col + j];
        }
        if (LEAKY) {
#pragma unroll
            for (int j = 0; j < 8; j++) v[j] = v[j] >= 0.f ? v[j] : 0.01f * v[j];
        }
        if (QKV) {
            int h = col >> 5, vv = col & 31;
            float* dst = C + (size_t)h * NN * VV + row * VV + vv;
            *(float4*)dst = make_float4(v[0], v[1], v[2], v[3]);
            *(float4*)(dst + 4) = make_float4(v[4], v[5], v[6], v[7]);
        } else {
            if (HAS_RES) {
                float4 r0 = *(const float4*)&res[row * NOUT + col];
                float4 r1 = *(const float4*)&res[row * NOUT + col + 4];
                v[0] += r0.x; v[1] += r0.y; v[2] += r0.z; v[3] += r0.w;
                v[4] += r1.x; v[5] += r1.y; v[6] += r1.z; v[7] += r1.w;
            }
            *(float4*)&C[row * NOUT + col] = make_float4(v[0], v[1], v[2], v[3]);
            *(float4*)&C[row * NOUT + col + 4] = make_float4(v[4], v[5], v[6], v[7]);
        }
    }
}

__global__ __launch_bounds__(256, 1) void qkv_x2(const float* __restrict__ Wq,
                                                 const float* __restrict__ Wk,
                                                 const float* __restrict__ Wv,
                                                 int layer) {
    int which = blockIdx.z;
    const float* W = (which == 0 ? Wq : which == 1 ? Wk : Wv)
                     + (size_t)layer * HH * EE * VV;
    float* outp = which == 0 ? g_q : which == 1 ? g_k : g_v;
    gemm_x2_core<EE, HV, false, false, false, true>(g_z, W, nullptr, nullptr, outp);
}
__global__ __launch_bounds__(256, 1) void wo_x2(const float* __restrict__ B) {
    gemm_x2_core<HV, EE, false, false, true, false>(g_o, B, nullptr, g_z, g_u);
}
__global__ __launch_bounds__(256, 1) void ff1_x2(const float* __restrict__ B,
                                                 const float* __restrict__ bias) {
    gemm_x2_core<EE, E2, true, true, false, false>(g_an, B, bias, nullptr, g_h1);
}
__global__ __launch_bounds__(256, 1) void ff2_x2(const float* __restrict__ B,
                                                 const float* __restrict__ bias) {
    gemm_x2_core<E2, EE, true, false, true, false>(g_h1, B, bias, g_an, g_u);
}

// ------------------------------- flash attention -------------------------------
// Per block: one head, 64 queries, 64-key tiles. Softmax fully in registers
// (running m/l per-thread, shfl_xor reductions over the 16-lane half-warp);
// only P crosses smem for the PV transpose.
__global__ __launch_bounds__(256) void attn_kernel() {
    __shared__ float Qs[32][68];     // [d][q], pre-scaled
    __shared__ float Ks[32][68];     // [d][key]
    __shared__ float Vs[64][36];     // [key][d]
    __shared__ float Psh[64][68];    // P transposed: [key][q]
    int tid = threadIdx.x;
    int h = blockIdx.y;
    int q0 = blockIdx.x * 64;
    const float scale = 0.17677669529663687f;  // 1/sqrt(32)
    int r8 = tid >> 3;
    int c4 = (tid & 7) * 4;
    const float* qb = g_q + (size_t)h * NN * VV;
    const float* kb = g_k + (size_t)h * NN * VV;
    const float* vb = g_v + (size_t)h * NN * VV;
    {
        float4 qa = *(const float4*)&qb[(size_t)(q0 + r8) * VV + c4];
        float4 qc = *(const float4*)&qb[(size_t)(q0 + r8 + 32) * VV + c4];
        Qs[c4 + 0][r8] = qa.x * scale; Qs[c4 + 1][r8] = qa.y * scale;
        Qs[c4 + 2][r8] = qa.z * scale; Qs[c4 + 3][r8] = qa.w * scale;
        Qs[c4 + 0][r8 + 32] = qc.x * scale; Qs[c4 + 1][r8 + 32] = qc.y * scale;
        Qs[c4 + 2][r8 + 32] = qc.z * scale; Qs[c4 + 3][r8 + 32] = qc.w * scale;
    }
    int tr = tid >> 4;             // q rows tr*4+i
    int tc = tid & 15;             // keys tc*4+j (S); d-pair tc*2 (PV/out)
    int sq = tr * 4, sk = tc * 4;
    float m[4], l[4];
#pragma unroll
    for (int i = 0; i < 4; i++) { m[i] = -INFINITY; l[i] = 0.f; }
    ull oacc[4] = {0ull, 0ull, 0ull, 0ull};
    // NOTE: no pre-loop sync needed — Qs writes are ordered before any read
    // by the first in-loop __syncthreads() pair; softmax state is registers.

    for (int kt = 0; kt < NN / 64; kt++) {
        int k0 = kt * 64;
        float4 ka = *(const float4*)&kb[(size_t)(k0 + r8) * VV + c4];
        float4 kc = *(const float4*)&kb[(size_t)(k0 + r8 + 32) * VV + c4];
        float4 va = *(const float4*)&vb[(size_t)(k0 + r8) * VV + c4];
        float4 vc = *(const float4*)&vb[(size_t)(k0 + r8 + 32) * VV + c4];
        __syncthreads();   // prior PV done with Vs/Psh
        Ks[c4 + 0][r8] = ka.x; Ks[c4 + 1][r8] = ka.y;
        Ks[c4 + 2][r8] = ka.z; Ks[c4 + 3][r8] = ka.w;
        Ks[c4 + 0][r8 + 32] = kc.x; Ks[c4 + 1][r8 + 32] = kc.y;
        Ks[c4 + 2][r8 + 32] = kc.z; Ks[c4 + 3][r8 + 32] = kc.w;
        *(float4*)&Vs[r8][c4] = va;
        *(float4*)&Vs[r8 + 32][c4] = vc;
        __syncthreads();

        // S = Q K^T : 4 query rows x 2 packed key-pairs (f32x2)
        ull sp[4][2];
#pragma unroll
        for (int i = 0; i < 4; i++) { sp[i][0] = 0ull; sp[i][1] = 0ull; }
#pragma unroll 8
        for (int d = 0; d < 32; d++) {
            float4 a = *(const float4*)&Qs[d][sq];
            float4 b = *(const float4*)&Ks[d][sk];
            ull bp0 = pk2(b.x, b.y), bp1 = pk2(b.z, b.w);
            ull ap0 = pk2(a.x, a.x), ap1 = pk2(a.y, a.y);
            ull ap2 = pk2(a.z, a.z), ap3 = pk2(a.w, a.w);
            fma2(sp[0][0], ap0, bp0); fma2(sp[0][1], ap0, bp1);
            fma2(sp[1][0], ap1, bp0); fma2(sp[1][1], ap1, bp1);
            fma2(sp[2][0], ap2, bp0); fma2(sp[2][1], ap2, bp1);
            fma2(sp[3][0], ap3, bp0); fma2(sp[3][1], ap3, bp1);
        }
        float s[4][4];
#pragma unroll
        for (int i = 0; i < 4; i++) {
            float2 t0 = upk(sp[i][0]), t1 = upk(sp[i][1]);
            s[i][0] = t0.x; s[i][1] = t0.y; s[i][2] = t1.x; s[i][3] = t1.y;
        }

        // in-register online softmax (per q-row, reduce over 16 lanes = 64 keys)
        float corr[4];
#pragma unroll
        for (int i = 0; i < 4; i++) {
            float mx = fmaxf(fmaxf(s[i][0], s[i][1]), fmaxf(s[i][2], s[i][3]));
            mx = fmaxf(mx, __shfl_xor_sync(0xffffffffu, mx, 1));
            mx = fmaxf(mx, __shfl_xor_sync(0xffffffffu, mx, 2));
            mx = fmaxf(mx, __shfl_xor_sync(0xffffffffu, mx, 4));
            mx = fmaxf(mx, __shfl_xor_sync(0xffffffffu, mx, 8));
            float mnew = fmaxf(m[i], mx);
            float p0 = __expf(s[i][0] - mnew);
            float p1 = __expf(s[i][1] - mnew);
            float p2 = __expf(s[i][2] - mnew);
            float p3 = __expf(s[i][3] - mnew);
            s[i][0] = p0; s[i][1] = p1; s[i][2] = p2; s[i][3] = p3;
            float sum = (p0 + p1) + (p2 + p3);
            sum += __shfl_xor_sync(0xffffffffu, sum, 1);
            sum += __shfl_xor_sync(0xffffffffu, sum, 2);
            sum += __shfl_xor_sync(0xffffffffu, sum, 4);
            sum += __shfl_xor_sync(0xffffffffu, sum, 8);
            float cr = __expf(m[i] - mnew);
            corr[i] = cr;
            l[i] = l[i] * cr + sum;
            m[i] = mnew;
        }
        oacc[0] = mul2(oacc[0], pk2(corr[0], corr[0]));
        oacc[1] = mul2(oacc[1], pk2(corr[1], corr[1]));
        oacc[2] = mul2(oacc[2], pk2(corr[2], corr[2]));
        oacc[3] = mul2(oacc[3], pk2(corr[3], corr[3]));

        // exchange P through smem (transposed for PV)
#pragma unroll
        for (int j = 0; j < 4; j++)
            *(float4*)&Psh[sk + j][sq] = make_float4(s[0][j], s[1][j], s[2][j], s[3][j]);
        __syncthreads();

        // O += P @ V   (rows tr*4+i, packed d pair tc*2)
#pragma unroll 8
        for (int kj = 0; kj < 64; kj++) {
            float4 p = *(const float4*)&Psh[kj][sq];
            ull vvp = *(const ull*)&Vs[kj][tc * 2];
            fma2(oacc[0], pk2(p.x, p.x), vvp);
            fma2(oacc[1], pk2(p.y, p.y), vvp);
            fma2(oacc[2], pk2(p.z, p.z), vvp);
            fma2(oacc[3], pk2(p.w, p.w), vvp);
        }
    }
#pragma unroll
    for (int i = 0; i < 4; i++) {
        float inv = 1.f / l[i];
        float2 t = upk(oacc[i]);
        *(float2*)&g_o[(size_t)(q0 + tr * 4 + i) * HV + h * VV + tc * 2] =
            make_float2(t.x * inv, t.y * inv);
    }
}

// ------------------------------- layernorm ------------------------------------
// mean over E, unbiased std (ddof=1), NO eps. One block (256 thr) per row.
// float4 I/O; 2 syncs total (warp partials -> all threads sum 8 partials).
__device__ __forceinline__ void ln_core(const float* __restrict__ in,
                                        float* __restrict__ out) {
    __shared__ float reds[8];
    __shared__ float redv[8];
    int r = blockIdx.x, tid = threadIdx.x;
    const float4* x = (const float4*)(in + (size_t)r * EE);
    float4 v = x[tid];
    float s = (v.x + v.y) + (v.z + v.w);
#pragma unroll
    for (int o = 16; o > 0; o >>= 1) s += __shfl_xor_sync(0xffffffffu, s, o);
    if ((tid & 31) == 0) reds[tid >> 5] = s;
    __syncthreads();
    float tot = ((reds[0] + reds[1]) + (reds[2] + reds[3]))
              + ((reds[4] + reds[5]) + (reds[6] + reds[7]));
    float mean = tot * (1.f / 1024.f);
    float dx = v.x - mean, dy = v.y - mean, dz = v.z - mean, dw = v.w - mean;
    float d = (dx * dx + dy * dy) + (dz * dz + dw * dw);
#pragma unroll
    for (int o = 16; o > 0; o >>= 1) d += __shfl_xor_sync(0xffffffffu, d, o);
    if ((tid & 31) == 0) redv[tid >> 5] = d;
    __syncthreads();
    float var = ((redv[0] + redv[1]) + (redv[2] + redv[3]))
              + ((redv[4] + redv[5]) + (redv[6] + redv[7]));
    float rstd = 1.f / sqrtf(var * (1.f / 1023.f));
    float4* o4 = (float4*)(out + (size_t)r * EE);
    o4[tid] = make_float4(dx * rstd, dy * rstd, dz * rstd, dw * rstd);
}

__global__ __launch_bounds__(256) void ln_an_kernel() { ln_core(g_u, g_an); }
__global__ __launch_bounds__(256) void ln_z_kernel() { ln_core(g_u, g_z); }
__global__ __launch_bounds__(256) void ln_out_kernel(float* out) { ln_core(g_u, out); }

// ------------------------------- driver ---------------------------------------
extern "C" void kernel_launch(void* const* d_in, const int* in_sizes, int n_in,
                              void* d_out, int out_size) {
    const int*   context = (const int*)d_in[0];
    const float* table   = (const float*)d_in[1];
    const float* pos     = (const float*)d_in[2];
    const float* Wq      = (const float*)d_in[3];
    const float* Wk      = (const float*)d_in[4];
    const float* Wv      = (const float*)d_in[5];
    const float* Wo      = (const float*)d_in[6];
    const float* W1      = (const float*)d_in[7];
    const float* b1      = (const float*)d_in[8];
    const float* W2      = (const float*)d_in[9];
    const float* b2      = (const float*)d_in[10];
    float* out = (float*)d_out;

    embed_kernel<<<NN, 256>>>(context, table, pos);
    for (int l = 0; l < LL; l++) {
        qkv_x2<<<dim3(NN / 128, HV / 128, 3), 256>>>(Wq, Wk, Wv, l);
        attn_kernel<<<dim3(NN / 64, HH), 256>>>();
        wo_x2<<<dim3(NN / 128, EE / 128), 256>>>(Wo + (size_t)l * HV * EE);
        ln_an_kernel<<<NN, 256>>>();
        ff1_x2<<<dim3(NN / 128, E2 / 128), 256>>>(W1 + (size_t)l * EE * E2,
                                                  b1 + (size_t)l * E2);
        ff2_x2<<<dim3(NN / 128, EE / 128), 256>>>(W2 + (size_t)l * E2 * EE,
                                                  b2 + (size_t)l * EE);
        if (l == LL - 1) ln_out_kernel<<<NN, 256>>>(out);
        else             ln_z_kernel<<<NN, 256>>>();
    }
}